// round 9
// baseline (speedup 1.0000x reference)
#include <cuda_runtime.h>
#include <math.h>

#define NB    2048
#define KDIM  256
#define PDIM  256
#define SDIM  10
#define NMAXC 512
#define TOPN  9
#define EPSF  1e-9f

// scratch: per-batch penalty (written fully every launch -> deterministic, no init needed)
__device__ float g_pen[NB];

__global__ __launch_bounds__(256) void per_batch_kernel(
    const float* __restrict__ y_pred,
    const float* __restrict__ P_padded,
    const float* __restrict__ params,
    const float* __restrict__ X)
{
    __shared__ float xs[SDIM][KDIM];    // 10 KB
    __shared__ float mag[SDIM][NMAXC];  // 20 KB
    __shared__ float hm_sh[SDIM];

    const int b   = blockIdx.x;
    const int tid = threadIdx.x;

    const int n  = (int)params[b * 3 + 0];
    const int m  = (int)params[b * 3 + 2];
    const int nk = n - KDIM;            // valid P columns, in [128, 256]

    // ---- stage X rows; K-part magnitudes are |X| (xmask all-true: k == K) ----
    const float* Xb = X + (size_t)b * SDIM * KDIM;
    #pragma unroll
    for (int it = 0; it < SDIM; it++) {
        int i = it * 256 + tid;
        float v = Xb[i];
        int s = i >> 8, k = i & 255;
        xs[s][k]  = v;
        mag[s][k] = fabsf(v);
    }
    __syncthreads();

    // ---- P part: thread p computes C[s, K+p] = X[s,:] . P[:,p] for all s ----
    {
        const int p = tid;
        if (p < nk) {
            float acc[SDIM];
            #pragma unroll
            for (int s = 0; s < SDIM; s++) acc[s] = 0.0f;
            const float* Pb = P_padded + (size_t)b * KDIM * PDIM + p;
            #pragma unroll 8
            for (int k = 0; k < KDIM; k++) {
                float pv = __ldg(Pb + (size_t)k * PDIM);
                #pragma unroll
                for (int s = 0; s < SDIM; s++)
                    acc[s] = fmaf(xs[s][k], pv, acc[s]);
            }
            #pragma unroll
            for (int s = 0; s < SDIM; s++) mag[s][KDIM + p] = fabsf(acc[s]);
        } else {
            #pragma unroll
            for (int s = 0; s < SDIM; s++) mag[s][KDIM + p] = -1.0f;  // invalid cols rank last
        }
    }
    __syncthreads();

    // ---- top-9 selection per sample s: warp w handles s = w, w+8 ----
    const int w    = tid >> 5;
    const int lane = tid & 31;
    for (int s = w; s < SDIM; s += 8) {
        float t[TOPN];
        #pragma unroll
        for (int j = 0; j < TOPN; j++) t[j] = -2.0f;  // below the -1 sentinel

        // lane-local sorted-desc top-9 via fmax/fmin insertion network (all regs)
        for (int i = lane; i < NMAXC; i += 32) {
            float v = mag[s][i];
            #pragma unroll
            for (int j = 0; j < TOPN; j++) {
                float mx = fmaxf(t[j], v);
                v = fminf(t[j], v);
                t[j] = mx;
            }
        }
        // warp tree-merge. FIX vs previous round: source lanes (lane >= off) must
        // NOT mutate their lists while being read, so (a) read the partner's full
        // list before inserting anything, and (b) only lanes < off perform the
        // insertion. All lanes still execute the shfl (defined-behavior req).
        #pragma unroll
        for (int off = 16; off >= 1; off >>= 1) {
            float r[TOPN];
            #pragma unroll
            for (int j = 0; j < TOPN; j++)
                r[j] = __shfl_down_sync(0xffffffffu, t[j], off);
            if (lane < off) {
                #pragma unroll
                for (int j = 0; j < TOPN; j++) {
                    float v = r[j];
                    #pragma unroll
                    for (int q = 0; q < TOPN; q++) {
                        float mx = fmaxf(t[q], v);
                        v = fminf(t[q], v);
                        t[q] = mx;
                    }
                }
            }
        }
        if (lane == 0) {
            float cmax = t[0];
            float cm;
            switch (m) {            // m in [1,8]; static index keeps t[] in registers
                case 1: cm = t[1]; break;
                case 2: cm = t[2]; break;
                case 3: cm = t[3]; break;
                case 4: cm = t[4]; break;
                case 5: cm = t[5]; break;
                case 6: cm = t[6]; break;
                case 7: cm = t[7]; break;
                default: cm = t[8]; break;
            }
            hm_sh[s] = cmax / (cm + EPSF);
        }
    }
    __syncthreads();

    if (tid == 0) {
        float mh = hm_sh[0];
        #pragma unroll
        for (int s = 1; s < SDIM; s++) mh = fmaxf(mh, hm_sh[s]);
        float pen = ((m + 1) <= n) ? fmaxf(mh - y_pred[b], 0.0f) : 0.0f;
        g_pen[b] = pen;
    }
}

__global__ __launch_bounds__(256) void finalize_kernel(
    const float* __restrict__ y_pred,
    const float* __restrict__ y_true,
    float* __restrict__ out, int out_size)
{
    __shared__ float s1[256];
    __shared__ float s2[256];
    const int tid = threadIdx.x;
    float a1 = 0.0f, a2 = 0.0f;
    for (int b = tid; b < NB; b += 256) {
        float lp = log2f(fmaxf(y_pred[b], EPSF));
        float lt = log2f(fmaxf(y_true[b], EPSF));
        float d  = lt - lp;
        a1 = fmaf(d, d, a1);
        a2 += g_pen[b];
    }
    s1[tid] = a1;
    s2[tid] = a2;
    __syncthreads();
    #pragma unroll
    for (int off = 128; off >= 1; off >>= 1) {
        if (tid < off) { s1[tid] += s1[tid + off]; s2[tid] += s2[tid + off]; }
        __syncthreads();
    }
    if (tid == 0) {
        float logmse = s1[0] * (1.0f / NB);
        float viol   = s2[0] * (1.0f / NB);
        float total  = logmse + 0.5f * viol;
        if (out_size > 0) out[0] = total;
        if (out_size > 1) out[1] = logmse;
        if (out_size > 2) out[2] = viol;
    }
}

extern "C" void kernel_launch(void* const* d_in, const int* in_sizes, int n_in,
                              void* d_out, int out_size)
{
    const float* y_pred   = (const float*)d_in[0];
    const float* y_true   = (const float*)d_in[1];
    const float* P_padded = (const float*)d_in[2];
    const float* params   = (const float*)d_in[3];
    const float* X        = (const float*)d_in[4];
    float* out = (float*)d_out;

    per_batch_kernel<<<NB, 256>>>(y_pred, P_padded, params, X);
    finalize_kernel<<<1, 256>>>(y_pred, y_true, out, out_size);
}

// round 10
// speedup vs baseline: 1.0285x; 1.0285x over previous
#include <cuda_runtime.h>
#include <math.h>

#define NB    2048
#define KDIM  256
#define PDIM  256
#define SDIM  10
#define NMAXC 512
#define TOPN  9
#define EPSF  1e-9f

// scratch: per-batch penalty (written fully every launch -> deterministic, no init needed)
__device__ float g_pen[NB];

__global__ __launch_bounds__(256) void per_batch_kernel(
    const float* __restrict__ y_pred,
    const float* __restrict__ P_padded,
    const float* __restrict__ params,
    const float* __restrict__ X)
{
    __shared__ __align__(16) float xs[SDIM][KDIM];   // 10 KB
    __shared__ float mag[SDIM][NMAXC];               // 20 KB
    __shared__ float hm_sh[SDIM];

    const int b   = blockIdx.x;
    const int tid = threadIdx.x;

    const int n  = (int)params[b * 3 + 0];
    const int m  = (int)params[b * 3 + 2];
    const int nk = n - KDIM;            // valid P columns, in [128, 256]

    // ---- stage X rows; K-part magnitudes are |X| (xmask all-true: k == K) ----
    const float* Xb = X + (size_t)b * SDIM * KDIM;
    #pragma unroll
    for (int it = 0; it < SDIM; it++) {
        int i = it * 256 + tid;
        float v = Xb[i];
        int s = i >> 8, k = i & 255;
        xs[s][k]  = v;
        mag[s][k] = fabsf(v);
    }
    __syncthreads();

    // ---- P part: thread p computes C[s, K+p] = X[s,:] . P[:,p] for all s ----
    // k processed in chunks of 4; xs read as float4 (cuts LDS wavefronts 4x,
    // which was the measured bottleneck). Accumulation order over k unchanged
    // vs the scalar version -> bit-identical numerics.
    {
        const int p = tid;
        if (p < nk) {
            float acc[SDIM];
            #pragma unroll
            for (int s = 0; s < SDIM; s++) acc[s] = 0.0f;
            const float* Pb = P_padded + (size_t)b * KDIM * PDIM + p;
            #pragma unroll 2
            for (int k0 = 0; k0 < KDIM; k0 += 4) {
                // 4 independent global loads (stride PDIM) -> MLP >= 4
                float pv0 = __ldg(Pb + (size_t)(k0 + 0) * PDIM);
                float pv1 = __ldg(Pb + (size_t)(k0 + 1) * PDIM);
                float pv2 = __ldg(Pb + (size_t)(k0 + 2) * PDIM);
                float pv3 = __ldg(Pb + (size_t)(k0 + 3) * PDIM);
                #pragma unroll
                for (int s = 0; s < SDIM; s++) {
                    float4 xv = *reinterpret_cast<const float4*>(&xs[s][k0]);
                    float a = acc[s];
                    a = fmaf(xv.x, pv0, a);
                    a = fmaf(xv.y, pv1, a);
                    a = fmaf(xv.z, pv2, a);
                    a = fmaf(xv.w, pv3, a);
                    acc[s] = a;
                }
            }
            #pragma unroll
            for (int s = 0; s < SDIM; s++) mag[s][KDIM + p] = fabsf(acc[s]);
        } else {
            #pragma unroll
            for (int s = 0; s < SDIM; s++) mag[s][KDIM + p] = -1.0f;  // invalid cols rank last
        }
    }
    __syncthreads();

    // ---- top-9 selection per sample s: warp w handles s = w, w+8 ----
    const int w    = tid >> 5;
    const int lane = tid & 31;
    for (int s = w; s < SDIM; s += 8) {
        float t[TOPN];
        #pragma unroll
        for (int j = 0; j < TOPN; j++) t[j] = -2.0f;  // below the -1 sentinel

        // lane-local sorted-desc top-9 via fmax/fmin insertion network (all regs)
        for (int i = lane; i < NMAXC; i += 32) {
            float v = mag[s][i];
            #pragma unroll
            for (int j = 0; j < TOPN; j++) {
                float mx = fmaxf(t[j], v);
                v = fminf(t[j], v);
                t[j] = mx;
            }
        }
        // warp tree-merge: read partner's full list first; only lanes < off insert
        // (source lanes must not mutate their lists while being read).
        #pragma unroll
        for (int off = 16; off >= 1; off >>= 1) {
            float r[TOPN];
            #pragma unroll
            for (int j = 0; j < TOPN; j++)
                r[j] = __shfl_down_sync(0xffffffffu, t[j], off);
            if (lane < off) {
                #pragma unroll
                for (int j = 0; j < TOPN; j++) {
                    float v = r[j];
                    #pragma unroll
                    for (int q = 0; q < TOPN; q++) {
                        float mx = fmaxf(t[q], v);
                        v = fminf(t[q], v);
                        t[q] = mx;
                    }
                }
            }
        }
        if (lane == 0) {
            float cmax = t[0];
            float cm;
            switch (m) {            // m in [1,8]; static index keeps t[] in registers
                case 1: cm = t[1]; break;
                case 2: cm = t[2]; break;
                case 3: cm = t[3]; break;
                case 4: cm = t[4]; break;
                case 5: cm = t[5]; break;
                case 6: cm = t[6]; break;
                case 7: cm = t[7]; break;
                default: cm = t[8]; break;
            }
            hm_sh[s] = cmax / (cm + EPSF);
        }
    }
    __syncthreads();

    if (tid == 0) {
        float mh = hm_sh[0];
        #pragma unroll
        for (int s = 1; s < SDIM; s++) mh = fmaxf(mh, hm_sh[s]);
        float pen = ((m + 1) <= n) ? fmaxf(mh - y_pred[b], 0.0f) : 0.0f;
        g_pen[b] = pen;
    }
}

__global__ __launch_bounds__(256) void finalize_kernel(
    const float* __restrict__ y_pred,
    const float* __restrict__ y_true,
    float* __restrict__ out, int out_size)
{
    __shared__ float s1[256];
    __shared__ float s2[256];
    const int tid = threadIdx.x;
    float a1 = 0.0f, a2 = 0.0f;
    for (int b = tid; b < NB; b += 256) {
        float lp = log2f(fmaxf(y_pred[b], EPSF));
        float lt = log2f(fmaxf(y_true[b], EPSF));
        float d  = lt - lp;
        a1 = fmaf(d, d, a1);
        a2 += g_pen[b];
    }
    s1[tid] = a1;
    s2[tid] = a2;
    __syncthreads();
    #pragma unroll
    for (int off = 128; off >= 1; off >>= 1) {
        if (tid < off) { s1[tid] += s1[tid + off]; s2[tid] += s2[tid + off]; }
        __syncthreads();
    }
    if (tid == 0) {
        float logmse = s1[0] * (1.0f / NB);
        float viol   = s2[0] * (1.0f / NB);
        float total  = logmse + 0.5f * viol;
        if (out_size > 0) out[0] = total;
        if (out_size > 1) out[1] = logmse;
        if (out_size > 2) out[2] = viol;
    }
}

extern "C" void kernel_launch(void* const* d_in, const int* in_sizes, int n_in,
                              void* d_out, int out_size)
{
    const float* y_pred   = (const float*)d_in[0];
    const float* y_true   = (const float*)d_in[1];
    const float* P_padded = (const float*)d_in[2];
    const float* params   = (const float*)d_in[3];
    const float* X        = (const float*)d_in[4];
    float* out = (float*)d_out;

    per_batch_kernel<<<NB, 256>>>(y_pred, P_padded, params, X);
    finalize_kernel<<<1, 256>>>(y_pred, y_true, out, out_size);
}

// round 11
// speedup vs baseline: 1.4635x; 1.4229x over previous
#include <cuda_runtime.h>
#include <math.h>

#define NB    2048
#define KDIM  256
#define PDIM  256
#define SDIM  10
#define NMAXC 512
#define TOPN  9
#define EPSF  1e-9f

// scratch: per-batch penalty (written fully every launch -> deterministic, no init needed)
__device__ float g_pen[NB];

// one f32x2 packed FMA: d.lo += a.lo*b.lo, d.hi += a.hi*b.hi (exact fp32 per lane)
__device__ __forceinline__ void ffma2(unsigned long long& d,
                                      unsigned long long a,
                                      unsigned long long b) {
    asm("fma.rn.f32x2 %0, %1, %2, %0;" : "+l"(d) : "l"(a), "l"(b));
}

__global__ __launch_bounds__(256) void per_batch_kernel(
    const float* __restrict__ y_pred,
    const float* __restrict__ P_padded,
    const float* __restrict__ params,
    const float* __restrict__ X)
{
    // xsp[k][s]: X transposed so sample-pairs (s,s+1) are contiguous 8-byte lanes.
    // Row stride 12 floats = 48 B -> every row 16B-aligned (for LDS.128 at +0,+16
    // and LDS.64 at +32). Slots 10,11 are padding, never read.
    __shared__ __align__(16) float xsp[KDIM][12];    // 12 KB
    __shared__ float mag[SDIM][NMAXC];               // 20 KB
    __shared__ float hm_sh[SDIM];

    const int b   = blockIdx.x;
    const int tid = threadIdx.x;

    const int n  = (int)params[b * 3 + 0];
    const int m  = (int)params[b * 3 + 2];
    const int nk = n - KDIM;            // valid P columns, in [128, 256]

    // ---- stage X (transposed); K-part magnitudes are |X| (xmask all-true) ----
    const float* Xb = X + (size_t)b * SDIM * KDIM;
    #pragma unroll
    for (int it = 0; it < SDIM; it++) {
        int i = it * 256 + tid;
        float v = Xb[i];
        int s = i >> 8, k = i & 255;
        xsp[k][s] = v;
        mag[s][k] = fabsf(v);
    }
    __syncthreads();

    // ---- P part: thread p computes C[s, K+p] = X[s,:] . P[:,p] for all s.
    // 5 packed f32x2 accumulators (sample pairs); per-lane fp32 FMA with the
    // same k-order as the scalar version -> bit-identical numerics, half the
    // FFMA issue slots (FFMA2 carries 2 FLOPs/instr; 3-reg FFMA is half-rate). ----
    {
        const int p = tid;
        if (p < nk) {
            unsigned long long a01 = 0ull, a23 = 0ull, a45 = 0ull,
                               a67 = 0ull, a89 = 0ull;   // (0.0f, 0.0f) pairs
            const float* Pb = P_padded + (size_t)b * KDIM * PDIM + p;
            #pragma unroll 2
            for (int k0 = 0; k0 < KDIM; k0 += 4) {
                // 4 independent coalesced global loads -> MLP >= 4
                float pv0 = __ldg(Pb + (size_t)(k0 + 0) * PDIM);
                float pv1 = __ldg(Pb + (size_t)(k0 + 1) * PDIM);
                float pv2 = __ldg(Pb + (size_t)(k0 + 2) * PDIM);
                float pv3 = __ldg(Pb + (size_t)(k0 + 3) * PDIM);
                float pvs[4] = {pv0, pv1, pv2, pv3};
                #pragma unroll
                for (int j = 0; j < 4; j++) {
                    const int k = k0 + j;
                    unsigned long long pvv;
                    asm("mov.b64 %0, {%1, %1};" : "=l"(pvv) : "f"(pvs[j]));
                    const ulonglong2 xa =
                        *reinterpret_cast<const ulonglong2*>(&xsp[k][0]); // s01, s23
                    const ulonglong2 xb =
                        *reinterpret_cast<const ulonglong2*>(&xsp[k][4]); // s45, s67
                    const unsigned long long xc =
                        *reinterpret_cast<const unsigned long long*>(&xsp[k][8]); // s89
                    ffma2(a01, xa.x, pvv);
                    ffma2(a23, xa.y, pvv);
                    ffma2(a45, xb.x, pvv);
                    ffma2(a67, xb.y, pvv);
                    ffma2(a89, xc,   pvv);
                }
            }
            float lo, hi;
            asm("mov.b64 {%0,%1}, %2;" : "=f"(lo), "=f"(hi) : "l"(a01));
            mag[0][KDIM + p] = fabsf(lo); mag[1][KDIM + p] = fabsf(hi);
            asm("mov.b64 {%0,%1}, %2;" : "=f"(lo), "=f"(hi) : "l"(a23));
            mag[2][KDIM + p] = fabsf(lo); mag[3][KDIM + p] = fabsf(hi);
            asm("mov.b64 {%0,%1}, %2;" : "=f"(lo), "=f"(hi) : "l"(a45));
            mag[4][KDIM + p] = fabsf(lo); mag[5][KDIM + p] = fabsf(hi);
            asm("mov.b64 {%0,%1}, %2;" : "=f"(lo), "=f"(hi) : "l"(a67));
            mag[6][KDIM + p] = fabsf(lo); mag[7][KDIM + p] = fabsf(hi);
            asm("mov.b64 {%0,%1}, %2;" : "=f"(lo), "=f"(hi) : "l"(a89));
            mag[8][KDIM + p] = fabsf(lo); mag[9][KDIM + p] = fabsf(hi);
        } else {
            #pragma unroll
            for (int s = 0; s < SDIM; s++) mag[s][KDIM + p] = -1.0f;  // invalid cols rank last
        }
    }
    __syncthreads();

    // ---- top-9 selection per sample s: warp w handles s = w, w+8 ----
    const int w    = tid >> 5;
    const int lane = tid & 31;
    for (int s = w; s < SDIM; s += 8) {
        float t[TOPN];
        #pragma unroll
        for (int j = 0; j < TOPN; j++) t[j] = -2.0f;  // below the -1 sentinel

        // lane-local sorted-desc top-9 via fmax/fmin insertion network (all regs)
        for (int i = lane; i < NMAXC; i += 32) {
            float v = mag[s][i];
            #pragma unroll
            for (int j = 0; j < TOPN; j++) {
                float mx = fmaxf(t[j], v);
                v = fminf(t[j], v);
                t[j] = mx;
            }
        }
        // warp tree-merge: read partner's full list first; only lanes < off insert
        // (source lanes must not mutate their lists while being read).
        #pragma unroll
        for (int off = 16; off >= 1; off >>= 1) {
            float r[TOPN];
            #pragma unroll
            for (int j = 0; j < TOPN; j++)
                r[j] = __shfl_down_sync(0xffffffffu, t[j], off);
            if (lane < off) {
                #pragma unroll
                for (int j = 0; j < TOPN; j++) {
                    float v = r[j];
                    #pragma unroll
                    for (int q = 0; q < TOPN; q++) {
                        float mx = fmaxf(t[q], v);
                        v = fminf(t[q], v);
                        t[q] = mx;
                    }
                }
            }
        }
        if (lane == 0) {
            float cmax = t[0];
            float cm;
            switch (m) {            // m in [1,8]; static index keeps t[] in registers
                case 1: cm = t[1]; break;
                case 2: cm = t[2]; break;
                case 3: cm = t[3]; break;
                case 4: cm = t[4]; break;
                case 5: cm = t[5]; break;
                case 6: cm = t[6]; break;
                case 7: cm = t[7]; break;
                default: cm = t[8]; break;
            }
            hm_sh[s] = cmax / (cm + EPSF);
        }
    }
    __syncthreads();

    if (tid == 0) {
        float mh = hm_sh[0];
        #pragma unroll
        for (int s = 1; s < SDIM; s++) mh = fmaxf(mh, hm_sh[s]);
        float pen = ((m + 1) <= n) ? fmaxf(mh - y_pred[b], 0.0f) : 0.0f;
        g_pen[b] = pen;
    }
}

__global__ __launch_bounds__(256) void finalize_kernel(
    const float* __restrict__ y_pred,
    const float* __restrict__ y_true,
    float* __restrict__ out, int out_size)
{
    __shared__ float s1[256];
    __shared__ float s2[256];
    const int tid = threadIdx.x;
    float a1 = 0.0f, a2 = 0.0f;
    for (int b = tid; b < NB; b += 256) {
        float lp = log2f(fmaxf(y_pred[b], EPSF));
        float lt = log2f(fmaxf(y_true[b], EPSF));
        float d  = lt - lp;
        a1 = fmaf(d, d, a1);
        a2 += g_pen[b];
    }
    s1[tid] = a1;
    s2[tid] = a2;
    __syncthreads();
    #pragma unroll
    for (int off = 128; off >= 1; off >>= 1) {
        if (tid < off) { s1[tid] += s1[tid + off]; s2[tid] += s2[tid + off]; }
        __syncthreads();
    }
    if (tid == 0) {
        float logmse = s1[0] * (1.0f / NB);
        float viol   = s2[0] * (1.0f / NB);
        float total  = logmse + 0.5f * viol;
        if (out_size > 0) out[0] = total;
        if (out_size > 1) out[1] = logmse;
        if (out_size > 2) out[2] = viol;
    }
}

extern "C" void kernel_launch(void* const* d_in, const int* in_sizes, int n_in,
                              void* d_out, int out_size)
{
    const float* y_pred   = (const float*)d_in[0];
    const float* y_true   = (const float*)d_in[1];
    const float* P_padded = (const float*)d_in[2];
    const float* params   = (const float*)d_in[3];
    const float* X        = (const float*)d_in[4];
    float* out = (float*)d_out;

    per_batch_kernel<<<NB, 256>>>(y_pred, P_padded, params, X);
    finalize_kernel<<<1, 256>>>(y_pred, y_true, out, out_size);
}

// round 15
// speedup vs baseline: 1.6689x; 1.1403x over previous
#include <cuda_runtime.h>
#include <math.h>

#define NB    2048
#define KDIM  256
#define PDIM  256
#define SDIM  10
#define NMAXC 512
#define EPSF  1e-9f

// scratch: per-batch penalty (written fully every launch -> deterministic, no init needed)
__device__ float g_pen[NB];

// one f32x2 packed FMA: d.lo += a.lo*b.lo, d.hi += a.hi*b.hi (exact fp32 per lane)
__device__ __forceinline__ void ffma2(unsigned long long& d,
                                      unsigned long long a,
                                      unsigned long long b) {
    asm("fma.rn.f32x2 %0, %1, %2, %0;" : "+l"(d) : "l"(a), "l"(b));
}

// Warp-cooperative top-D selection over mag[0..511] (32 lanes x 16 values).
// Returns (on lane 0) t0/(t[D-1]+eps) = c_max/(c_m+eps) with D = m+1.
// Exact top-k: insertion networks + sorted-list tree merge. The merge inner
// loop starts at q=j because the partner's j-th sorted element cannot rank
// above position j once r[0..j-1] (all >= r[j]) are already inserted.
template <int D>
__device__ __forceinline__ float warp_select_ratio(const float* __restrict__ magrow,
                                                   int lane)
{
    float t[D];
    #pragma unroll
    for (int j = 0; j < D; j++) t[j] = -2.0f;   // below the -1 sentinel

    #pragma unroll
    for (int it = 0; it < NMAXC / 32; it++) {
        float v = magrow[it * 32 + lane];
        #pragma unroll
        for (int j = 0; j < D; j++) {
            float mx = fmaxf(t[j], v);
            v = fminf(t[j], v);
            t[j] = mx;
        }
    }
    // tree merge: read partner's full sorted list first; only lanes < off insert
    #pragma unroll
    for (int off = 16; off >= 1; off >>= 1) {
        float r[D];
        #pragma unroll
        for (int j = 0; j < D; j++)
            r[j] = __shfl_down_sync(0xffffffffu, t[j], off);
        if (lane < off) {
            #pragma unroll
            for (int j = 0; j < D; j++) {
                float v = r[j];
                #pragma unroll
                for (int q = 0; q < D; q++) {
                    if (q >= j) {                 // triangular: r[j] ranks >= j
                        float mx = fmaxf(t[q], v);
                        v = fminf(t[q], v);
                        t[q] = mx;
                    }
                }
            }
        }
    }
    return t[0] / (t[D - 1] + EPSF);
}

__global__ __launch_bounds__(256) void per_batch_kernel(
    const float* __restrict__ y_pred,
    const float* __restrict__ P_padded,
    const float* __restrict__ params,
    const float* __restrict__ X)
{
    // xsp[k][s]: X transposed so sample-pairs (s,s+1) are contiguous 8-byte lanes.
    // Row stride 12 floats = 48 B -> every row 16B-aligned (LDS.128 at +0,+16,
    // LDS.64 at +32). Slots 10,11 are padding, never read.
    __shared__ __align__(16) float xsp[KDIM][12];    // 12 KB
    __shared__ float mag[SDIM][NMAXC];               // 20 KB
    __shared__ float hm_sh[SDIM];

    const int b   = blockIdx.x;
    const int tid = threadIdx.x;

    const int n  = (int)params[b * 3 + 0];
    int m        = (int)params[b * 3 + 2];
    if (m < 1) m = 1; if (m > 8) m = 8;          // setup guarantees [1,8]
    const int nk = n - KDIM;                     // valid P columns, in [128, 256]

    // ---- stage X (transposed); K-part magnitudes are |X| (xmask all-true) ----
    const float* Xb = X + (size_t)b * SDIM * KDIM;
    #pragma unroll
    for (int it = 0; it < SDIM; it++) {
        int i = it * 256 + tid;
        float v = Xb[i];
        int s = i >> 8, k = i & 255;
        xsp[k][s] = v;
        mag[s][k] = fabsf(v);
    }
    __syncthreads();

    // ---- P part: thread p computes C[s, K+p] = X[s,:] . P[:,p] for all s.
    // 5 packed f32x2 accumulators (sample pairs); per-lane fp32 FMA, same
    // k-order as scalar -> bit-identical numerics, half the FFMA issue slots. ----
    {
        const int p = tid;
        if (p < nk) {
            unsigned long long a01 = 0ull, a23 = 0ull, a45 = 0ull,
                               a67 = 0ull, a89 = 0ull;   // (0.0f, 0.0f) pairs
            const float* Pb = P_padded + (size_t)b * KDIM * PDIM + p;
            #pragma unroll 2
            for (int k0 = 0; k0 < KDIM; k0 += 4) {
                float pv0 = __ldg(Pb + (size_t)(k0 + 0) * PDIM);
                float pv1 = __ldg(Pb + (size_t)(k0 + 1) * PDIM);
                float pv2 = __ldg(Pb + (size_t)(k0 + 2) * PDIM);
                float pv3 = __ldg(Pb + (size_t)(k0 + 3) * PDIM);
                float pvs[4] = {pv0, pv1, pv2, pv3};
                #pragma unroll
                for (int j = 0; j < 4; j++) {
                    const int k = k0 + j;
                    unsigned long long pvv;
                    asm("mov.b64 %0, {%1, %1};" : "=l"(pvv) : "f"(pvs[j]));
                    const ulonglong2 xa =
                        *reinterpret_cast<const ulonglong2*>(&xsp[k][0]); // s01, s23
                    const ulonglong2 xb =
                        *reinterpret_cast<const ulonglong2*>(&xsp[k][4]); // s45, s67
                    const unsigned long long xc =
                        *reinterpret_cast<const unsigned long long*>(&xsp[k][8]); // s89
                    ffma2(a01, xa.x, pvv);
                    ffma2(a23, xa.y, pvv);
                    ffma2(a45, xb.x, pvv);
                    ffma2(a67, xb.y, pvv);
                    ffma2(a89, xc,   pvv);
                }
            }
            float lo, hi;
            asm("mov.b64 {%0,%1}, %2;" : "=f"(lo), "=f"(hi) : "l"(a01));
            mag[0][KDIM + p] = fabsf(lo); mag[1][KDIM + p] = fabsf(hi);
            asm("mov.b64 {%0,%1}, %2;" : "=f"(lo), "=f"(hi) : "l"(a23));
            mag[2][KDIM + p] = fabsf(lo); mag[3][KDIM + p] = fabsf(hi);
            asm("mov.b64 {%0,%1}, %2;" : "=f"(lo), "=f"(hi) : "l"(a45));
            mag[4][KDIM + p] = fabsf(lo); mag[5][KDIM + p] = fabsf(hi);
            asm("mov.b64 {%0,%1}, %2;" : "=f"(lo), "=f"(hi) : "l"(a67));
            mag[6][KDIM + p] = fabsf(lo); mag[7][KDIM + p] = fabsf(hi);
            asm("mov.b64 {%0,%1}, %2;" : "=f"(lo), "=f"(hi) : "l"(a89));
            mag[8][KDIM + p] = fabsf(lo); mag[9][KDIM + p] = fabsf(hi);
        } else {
            #pragma unroll
            for (int s = 0; s < SDIM; s++) mag[s][KDIM + p] = -1.0f;  // invalid cols rank last
        }
    }
    __syncthreads();

    // ---- top-(m+1) selection per sample s: warp w handles s = w, w+8.
    // m is uniform across the block -> single switch, no divergence. ----
    const int w    = tid >> 5;
    const int lane = tid & 31;
    for (int s = w; s < SDIM; s += 8) {
        const float* magrow = mag[s];
        float hm;
        switch (m) {
            case 1:  hm = warp_select_ratio<2>(magrow, lane); break;
            case 2:  hm = warp_select_ratio<3>(magrow, lane); break;
            case 3:  hm = warp_select_ratio<4>(magrow, lane); break;
            case 4:  hm = warp_select_ratio<5>(magrow, lane); break;
            case 5:  hm = warp_select_ratio<6>(magrow, lane); break;
            case 6:  hm = warp_select_ratio<7>(magrow, lane); break;
            case 7:  hm = warp_select_ratio<8>(magrow, lane); break;
            default: hm = warp_select_ratio<9>(magrow, lane); break;
        }
        if (lane == 0) hm_sh[s] = hm;
    }
    __syncthreads();

    if (tid == 0) {
        float mh = hm_sh[0];
        #pragma unroll
        for (int s = 1; s < SDIM; s++) mh = fmaxf(mh, hm_sh[s]);
        float pen = ((m + 1) <= n) ? fmaxf(mh - y_pred[b], 0.0f) : 0.0f;
        g_pen[b] = pen;
    }
}

__global__ __launch_bounds__(256) void finalize_kernel(
    const float* __restrict__ y_pred,
    const float* __restrict__ y_true,
    float* __restrict__ out, int out_size)
{
    __shared__ float s1[256];
    __shared__ float s2[256];
    const int tid = threadIdx.x;
    float a1 = 0.0f, a2 = 0.0f;
    for (int b = tid; b < NB; b += 256) {
        float lp = log2f(fmaxf(y_pred[b], EPSF));
        float lt = log2f(fmaxf(y_true[b], EPSF));
        float d  = lt - lp;
        a1 = fmaf(d, d, a1);
        a2 += g_pen[b];
    }
    s1[tid] = a1;
    s2[tid] = a2;
    __syncthreads();
    #pragma unroll
    for (int off = 128; off >= 1; off >>= 1) {
        if (tid < off) { s1[tid] += s1[tid + off]; s2[tid] += s2[tid + off]; }
        __syncthreads();
    }
    if (tid == 0) {
        float logmse = s1[0] * (1.0f / NB);
        float viol   = s2[0] * (1.0f / NB);
        float total  = logmse + 0.5f * viol;
        if (out_size > 0) out[0] = total;
        if (out_size > 1) out[1] = logmse;
        if (out_size > 2) out[2] = viol;
    }
}

extern "C" void kernel_launch(void* const* d_in, const int* in_sizes, int n_in,
                              void* d_out, int out_size)
{
    const float* y_pred   = (const float*)d_in[0];
    const float* y_true   = (const float*)d_in[1];
    const float* P_padded = (const float*)d_in[2];
    const float* params   = (const float*)d_in[3];
    const float* X        = (const float*)d_in[4];
    float* out = (float*)d_out;

    per_batch_kernel<<<NB, 256>>>(y_pred, P_padded, params, X);
    finalize_kernel<<<1, 256>>>(y_pred, y_true, out, out_size);
}

// round 16
// speedup vs baseline: 1.6717x; 1.0017x over previous
#include <cuda_runtime.h>
#include <math.h>

#define NB    2048
#define KDIM  256
#define PDIM  256
#define SDIM  10
#define NMAXC 512
#define EPSF  1e-9f

// scratch: per-batch penalty + completion counter (reset by last block each launch)
__device__ float g_pen[NB];
__device__ unsigned int g_done = 0;

// one f32x2 packed FMA: d.lo += a.lo*b.lo, d.hi += a.hi*b.hi (exact fp32 per lane)
__device__ __forceinline__ void ffma2(unsigned long long& d,
                                      unsigned long long a,
                                      unsigned long long b) {
    asm("fma.rn.f32x2 %0, %1, %2, %0;" : "+l"(d) : "l"(a), "l"(b));
}

// Warp-cooperative top-D selection over mag[0..511] (32 lanes x 16 values).
// Returns (on lane 0) t0/(t[D-1]+eps) = c_max/(c_m+eps) with D = m+1.
// Exact top-k: insertion networks + sorted-list tree merge. The merge inner
// loop starts at q=j because the partner's j-th sorted element cannot rank
// above position j once r[0..j-1] (all >= r[j]) are already inserted.
template <int D>
__device__ __forceinline__ float warp_select_ratio(const float* __restrict__ magrow,
                                                   int lane)
{
    float t[D];
    #pragma unroll
    for (int j = 0; j < D; j++) t[j] = -2.0f;   // below the -1 sentinel

    #pragma unroll
    for (int it = 0; it < NMAXC / 32; it++) {
        float v = magrow[it * 32 + lane];
        #pragma unroll
        for (int j = 0; j < D; j++) {
            float mx = fmaxf(t[j], v);
            v = fminf(t[j], v);
            t[j] = mx;
        }
    }
    // tree merge: read partner's full sorted list first; only lanes < off insert
    #pragma unroll
    for (int off = 16; off >= 1; off >>= 1) {
        float r[D];
        #pragma unroll
        for (int j = 0; j < D; j++)
            r[j] = __shfl_down_sync(0xffffffffu, t[j], off);
        if (lane < off) {
            #pragma unroll
            for (int j = 0; j < D; j++) {
                float v = r[j];
                #pragma unroll
                for (int q = 0; q < D; q++) {
                    if (q >= j) {                 // triangular: r[j] ranks >= j
                        float mx = fmaxf(t[q], v);
                        v = fminf(t[q], v);
                        t[q] = mx;
                    }
                }
            }
        }
    }
    return t[0] / (t[D - 1] + EPSF);
}

__global__ __launch_bounds__(256) void per_batch_kernel(
    const float* __restrict__ y_pred,
    const float* __restrict__ y_true,
    const float* __restrict__ P_padded,
    const float* __restrict__ params,
    const float* __restrict__ X,
    float* __restrict__ out, int out_size)
{
    // xsp[k][s]: X transposed so sample-pairs (s,s+1) are contiguous 8-byte lanes.
    // Row stride 12 floats = 48 B -> every row 16B-aligned (LDS.128 at +0,+16,
    // LDS.64 at +32). Slots 10,11 are padding, never read.
    __shared__ __align__(16) float xsp[KDIM][12];    // 12 KB
    __shared__ float mag[SDIM][NMAXC];               // 20 KB
    __shared__ float hm_sh[SDIM];
    __shared__ int   is_last;

    const int b   = blockIdx.x;
    const int tid = threadIdx.x;

    const int n  = (int)params[b * 3 + 0];
    int m        = (int)params[b * 3 + 2];
    if (m < 1) m = 1; if (m > 8) m = 8;          // setup guarantees [1,8]
    const int nk = n - KDIM;                     // valid P columns, in [128, 256]

    // ---- stage X (transposed); K-part magnitudes are |X| (xmask all-true) ----
    const float* Xb = X + (size_t)b * SDIM * KDIM;
    #pragma unroll
    for (int it = 0; it < SDIM; it++) {
        int i = it * 256 + tid;
        float v = Xb[i];
        int s = i >> 8, k = i & 255;
        xsp[k][s] = v;
        mag[s][k] = fabsf(v);
    }
    __syncthreads();

    // ---- P part: thread p computes C[s, K+p] = X[s,:] . P[:,p] for all s.
    // 5 packed f32x2 accumulators (sample pairs); per-lane fp32 FMA, same
    // k-order as scalar -> bit-identical numerics, half the FFMA issue slots. ----
    {
        const int p = tid;
        if (p < nk) {
            unsigned long long a01 = 0ull, a23 = 0ull, a45 = 0ull,
                               a67 = 0ull, a89 = 0ull;   // (0.0f, 0.0f) pairs
            const float* Pb = P_padded + (size_t)b * KDIM * PDIM + p;
            #pragma unroll 2
            for (int k0 = 0; k0 < KDIM; k0 += 4) {
                float pv0 = __ldg(Pb + (size_t)(k0 + 0) * PDIM);
                float pv1 = __ldg(Pb + (size_t)(k0 + 1) * PDIM);
                float pv2 = __ldg(Pb + (size_t)(k0 + 2) * PDIM);
                float pv3 = __ldg(Pb + (size_t)(k0 + 3) * PDIM);
                float pvs[4] = {pv0, pv1, pv2, pv3};
                #pragma unroll
                for (int j = 0; j < 4; j++) {
                    const int k = k0 + j;
                    unsigned long long pvv;
                    asm("mov.b64 %0, {%1, %1};" : "=l"(pvv) : "f"(pvs[j]));
                    const ulonglong2 xa =
                        *reinterpret_cast<const ulonglong2*>(&xsp[k][0]); // s01, s23
                    const ulonglong2 xb =
                        *reinterpret_cast<const ulonglong2*>(&xsp[k][4]); // s45, s67
                    const unsigned long long xc =
                        *reinterpret_cast<const unsigned long long*>(&xsp[k][8]); // s89
                    ffma2(a01, xa.x, pvv);
                    ffma2(a23, xa.y, pvv);
                    ffma2(a45, xb.x, pvv);
                    ffma2(a67, xb.y, pvv);
                    ffma2(a89, xc,   pvv);
                }
            }
            float lo, hi;
            asm("mov.b64 {%0,%1}, %2;" : "=f"(lo), "=f"(hi) : "l"(a01));
            mag[0][KDIM + p] = fabsf(lo); mag[1][KDIM + p] = fabsf(hi);
            asm("mov.b64 {%0,%1}, %2;" : "=f"(lo), "=f"(hi) : "l"(a23));
            mag[2][KDIM + p] = fabsf(lo); mag[3][KDIM + p] = fabsf(hi);
            asm("mov.b64 {%0,%1}, %2;" : "=f"(lo), "=f"(hi) : "l"(a45));
            mag[4][KDIM + p] = fabsf(lo); mag[5][KDIM + p] = fabsf(hi);
            asm("mov.b64 {%0,%1}, %2;" : "=f"(lo), "=f"(hi) : "l"(a67));
            mag[6][KDIM + p] = fabsf(lo); mag[7][KDIM + p] = fabsf(hi);
            asm("mov.b64 {%0,%1}, %2;" : "=f"(lo), "=f"(hi) : "l"(a89));
            mag[8][KDIM + p] = fabsf(lo); mag[9][KDIM + p] = fabsf(hi);
        } else {
            #pragma unroll
            for (int s = 0; s < SDIM; s++) mag[s][KDIM + p] = -1.0f;  // invalid cols rank last
        }
    }
    __syncthreads();

    // ---- top-(m+1) selection per sample s: warp w handles s = w, w+8.
    // m is uniform across the block -> single switch, no divergence. ----
    const int w    = tid >> 5;
    const int lane = tid & 31;
    for (int s = w; s < SDIM; s += 8) {
        const float* magrow = mag[s];
        float hm;
        switch (m) {
            case 1:  hm = warp_select_ratio<2>(magrow, lane); break;
            case 2:  hm = warp_select_ratio<3>(magrow, lane); break;
            case 3:  hm = warp_select_ratio<4>(magrow, lane); break;
            case 4:  hm = warp_select_ratio<5>(magrow, lane); break;
            case 5:  hm = warp_select_ratio<6>(magrow, lane); break;
            case 6:  hm = warp_select_ratio<7>(magrow, lane); break;
            case 7:  hm = warp_select_ratio<8>(magrow, lane); break;
            default: hm = warp_select_ratio<9>(magrow, lane); break;
        }
        if (lane == 0) hm_sh[s] = hm;
    }
    __syncthreads();

    // ---- publish this block's penalty, then last-arriving block finalizes ----
    if (tid == 0) {
        float mh = hm_sh[0];
        #pragma unroll
        for (int s = 1; s < SDIM; s++) mh = fmaxf(mh, hm_sh[s]);
        float pen = ((m + 1) <= n) ? fmaxf(mh - y_pred[b], 0.0f) : 0.0f;
        g_pen[b] = pen;
        __threadfence();                              // publish before arrival
        unsigned int old = atomicAdd(&g_done, 1u);
        is_last = (old == NB - 1) ? 1 : 0;
    }
    __syncthreads();

    if (is_last) {
        // identical summation order to the old finalize_kernel -> bit-identical out
        __shared__ float s1[256];
        __shared__ float s2[256];
        float a1 = 0.0f, a2 = 0.0f;
        for (int i = tid; i < NB; i += 256) {
            float lp = log2f(fmaxf(y_pred[i], EPSF));
            float lt = log2f(fmaxf(y_true[i], EPSF));
            float d  = lt - lp;
            a1 = fmaf(d, d, a1);
            a2 += __ldcg(&g_pen[i]);                  // L2 read: skip any stale L1
        }
        s1[tid] = a1;
        s2[tid] = a2;
        __syncthreads();
        #pragma unroll
        for (int off = 128; off >= 1; off >>= 1) {
            if (tid < off) { s1[tid] += s1[tid + off]; s2[tid] += s2[tid + off]; }
            __syncthreads();
        }
        if (tid == 0) {
            float logmse = s1[0] * (1.0f / NB);
            float viol   = s2[0] * (1.0f / NB);
            float total  = logmse + 0.5f * viol;
            if (out_size > 0) out[0] = total;
            if (out_size > 1) out[1] = logmse;
            if (out_size > 2) out[2] = viol;
            g_done = 0;                                // reset for next graph replay
        }
    }
}

extern "C" void kernel_launch(void* const* d_in, const int* in_sizes, int n_in,
                              void* d_out, int out_size)
{
    const float* y_pred   = (const float*)d_in[0];
    const float* y_true   = (const float*)d_in[1];
    const float* P_padded = (const float*)d_in[2];
    const float* params   = (const float*)d_in[3];
    const float* X        = (const float*)d_in[4];
    float* out = (float*)d_out;

    per_batch_kernel<<<NB, 256>>>(y_pred, y_true, P_padded, params, X, out, out_size);
}